// round 4
// baseline (speedup 1.0000x reference)
#include <cuda_runtime.h>
#include <cuda_bf16.h>
#include <math.h>

#define NMAX 50000
#define EMAX 600000
#define DIM 128

// ---------------- scratch (device globals; no allocations allowed) ----------------
__device__ float g_q[NMAX * DIM];
__device__ float g_k[NMAX * DIM];
__device__ float g_v[NMAX * DIM];
__device__ float g_s[NMAX * DIM];
__device__ float g_h[NMAX * DIM];
__device__ float g_agg[NMAX * DIM];
__device__ float g_e[(size_t)EMAX * DIM];
__device__ float g_score[EMAX * 8];
__device__ float g_den[NMAX * 8];
__device__ unsigned g_smax[NMAX * 8];

// order-preserving float<->uint encoding for atomicMax on floats (incl. negatives)
__device__ __forceinline__ unsigned enc_f(float x) {
    unsigned s = __float_as_uint(x);
    unsigned mask = (unsigned)((int)s >> 31) | 0x80000000u;
    return s ^ mask;
}
__device__ __forceinline__ float dec_f(unsigned kk) {
    unsigned s = (kk & 0x80000000u) ? (kk ^ 0x80000000u) : ~kk;
    return __uint_as_float(s);
}

// ---------------- node GEMM: out[M,128] = A[M,128] @ W[128,128] + b ----------------
// 128x128 tile, 8x8 per thread, blockIdx.y selects one of 4 (W, b, out) triples.
__global__ __launch_bounds__(256) void gemm_qkvs(
    const float* __restrict__ A, int M,
    const float* __restrict__ W0, const float* __restrict__ W1,
    const float* __restrict__ W2, const float* __restrict__ W3,
    const float* __restrict__ b0, const float* __restrict__ b1,
    const float* __restrict__ b2, const float* __restrict__ b3,
    float* __restrict__ o0, float* __restrict__ o1,
    float* __restrict__ o2, float* __restrict__ o3)
{
    const float* W; const float* bias; float* O;
    switch (blockIdx.y) {
        case 0: W = W0; bias = b0; O = o0; break;
        case 1: W = W1; bias = b1; O = o1; break;
        case 2: W = W2; bias = b2; O = o2; break;
        default: W = W3; bias = b3; O = o3; break;
    }
    __shared__ float As[8][128];
    __shared__ float Bs[8][128];
    int tid = threadIdx.x;
    int tx = tid % 16, ty = tid / 16;
    int m0 = blockIdx.x * 128;

    float acc[8][8];
#pragma unroll
    for (int i = 0; i < 8; i++)
#pragma unroll
        for (int j = 0; j < 8; j++) acc[i][j] = 0.f;

    for (int k0 = 0; k0 < 128; k0 += 8) {
        // A tile: 128 rows x 8 k, 2 threads/row, float4 each
        {
            int row_l = tid >> 1;
            int kk = (tid & 1) * 4;
            int row = m0 + row_l;
            float4 av = make_float4(0.f, 0.f, 0.f, 0.f);
            if (row < M) av = *reinterpret_cast<const float4*>(A + (size_t)row * 128 + k0 + kk);
            As[kk + 0][row_l] = av.x;
            As[kk + 1][row_l] = av.y;
            As[kk + 2][row_l] = av.z;
            As[kk + 3][row_l] = av.w;
        }
        // B tile: 8 rows x 128 cols, linear float4
        {
            float4 bv = *reinterpret_cast<const float4*>(W + (size_t)k0 * 128 + tid * 4);
            int bkk = (tid * 4) >> 7;
            int bn = (tid * 4) & 127;
            Bs[bkk][bn + 0] = bv.x;
            Bs[bkk][bn + 1] = bv.y;
            Bs[bkk][bn + 2] = bv.z;
            Bs[bkk][bn + 3] = bv.w;
        }
        __syncthreads();
#pragma unroll
        for (int kk = 0; kk < 8; kk++) {
            float a[8], b[8];
#pragma unroll
            for (int i = 0; i < 8; i++) a[i] = As[kk][ty * 8 + i];
#pragma unroll
            for (int j = 0; j < 8; j++) b[j] = Bs[kk][tx * 8 + j];
#pragma unroll
            for (int i = 0; i < 8; i++)
#pragma unroll
                for (int j = 0; j < 8; j++) acc[i][j] = fmaf(a[i], b[j], acc[i][j]);
        }
        __syncthreads();
    }
#pragma unroll
    for (int i = 0; i < 8; i++) {
        int row = m0 + ty * 8 + i;
        if (row < M) {
#pragma unroll
            for (int j = 0; j < 8; j++) {
                int col = tx * 8 + j;
                O[(size_t)row * 128 + col] = acc[i][j] + bias[col];
            }
        }
    }
}

// ---------------- edge GEMM: e[E,128] = ea[E,16] @ We[16,128] + be ----------------
__global__ __launch_bounds__(256) void gemm_edge(
    const float* __restrict__ A, int E,
    const float* __restrict__ W, const float* __restrict__ bias,
    float* __restrict__ O)
{
    __shared__ float As[16][128];
    __shared__ float Ws_[16 * 128];
    int tid = threadIdx.x;
    int tx = tid % 16, ty = tid / 16;
    int m0 = blockIdx.x * 128;

    // load A tile (128 rows x 16) transposed, 2 float4 per thread
#pragma unroll
    for (int it = 0; it < 2; it++) {
        int g = tid * 2 + it;          // float4 index, 0..511
        int row_l = g >> 2;
        int kk = (g & 3) * 4;
        int row = m0 + row_l;
        float4 av = make_float4(0.f, 0.f, 0.f, 0.f);
        if (row < E) av = *reinterpret_cast<const float4*>(A + (size_t)row * 16 + kk);
        As[kk + 0][row_l] = av.x;
        As[kk + 1][row_l] = av.y;
        As[kk + 2][row_l] = av.z;
        As[kk + 3][row_l] = av.w;
    }
    // load W (16x128 contiguous)
#pragma unroll
    for (int it = 0; it < 2; it++) {
        int g = tid * 2 + it;
        reinterpret_cast<float4*>(Ws_)[g] = reinterpret_cast<const float4*>(W)[g];
    }
    __syncthreads();

    float acc[8][8];
#pragma unroll
    for (int i = 0; i < 8; i++)
#pragma unroll
        for (int j = 0; j < 8; j++) acc[i][j] = 0.f;

#pragma unroll
    for (int kk = 0; kk < 16; kk++) {
        float a[8], b[8];
#pragma unroll
        for (int i = 0; i < 8; i++) a[i] = As[kk][ty * 8 + i];
#pragma unroll
        for (int j = 0; j < 8; j++) b[j] = Ws_[kk * 128 + tx * 8 + j];
#pragma unroll
        for (int i = 0; i < 8; i++)
#pragma unroll
            for (int j = 0; j < 8; j++) acc[i][j] = fmaf(a[i], b[j], acc[i][j]);
    }
#pragma unroll
    for (int i = 0; i < 8; i++) {
        int row = m0 + ty * 8 + i;
        if (row < E) {
#pragma unroll
            for (int j = 0; j < 8; j++) {
                int col = tx * 8 + j;
                O[(size_t)row * 128 + col] = acc[i][j] + bias[col];
            }
        }
    }
}

// ---------------- attention score + segment max (warp per edge) ----------------
template <int H>
__global__ __launch_bounds__(256) void score_kernel(
    const int* __restrict__ ei, int E,
    const float* __restrict__ q, const float* __restrict__ k,
    const float* __restrict__ eemb,
    float* __restrict__ score, unsigned* __restrict__ smax, float scale)
{
    int warp = (blockIdx.x * blockDim.x + threadIdx.x) >> 5;
    int lane = threadIdx.x & 31;
    if (warp >= E) return;
    int src = ei[warp];
    int dst = ei[E + warp];
    float4 qv = *reinterpret_cast<const float4*>(q + (size_t)dst * 128 + lane * 4);
    float4 kv = *reinterpret_cast<const float4*>(k + (size_t)src * 128 + lane * 4);
    float4 ev = *reinterpret_cast<const float4*>(eemb + (size_t)warp * 128 + lane * 4);
    float s = qv.x * (kv.x + ev.x) + qv.y * (kv.y + ev.y) +
              qv.z * (kv.z + ev.z) + qv.w * (kv.w + ev.w);
    s += __shfl_xor_sync(0xFFFFFFFFu, s, 1);
    s += __shfl_xor_sync(0xFFFFFFFFu, s, 2);
    if (H == 1) {
        s += __shfl_xor_sync(0xFFFFFFFFu, s, 4);
        s += __shfl_xor_sync(0xFFFFFFFFu, s, 8);
        s += __shfl_xor_sync(0xFFFFFFFFu, s, 16);
        s *= scale;
        if (lane == 0) {
            score[warp] = s;
            atomicMax(&smax[dst], enc_f(s));
        }
    } else {  // H == 8, head = lane/4
        s *= scale;
        if ((lane & 3) == 0) {
            int h = lane >> 2;
            score[(size_t)warp * 8 + h] = s;
            atomicMax(&smax[dst * 8 + h], enc_f(s));
        }
    }
}

// ---------------- exp + segment denominator ----------------
template <int H>
__global__ __launch_bounds__(256) void expsum_kernel(
    const int* __restrict__ ei, int E,
    float* __restrict__ score, const unsigned* __restrict__ smax,
    float* __restrict__ den)
{
    int idx = blockIdx.x * blockDim.x + threadIdx.x;
    if (idx >= E * H) return;
    int e = (H == 1) ? idx : (idx >> 3);
    int h = (H == 1) ? 0 : (idx & 7);
    int dst = ei[E + e];
    float m = dec_f(smax[dst * H + h]);
    float ex = expf(score[idx] - m);
    score[idx] = ex;
    atomicAdd(&den[dst * H + h], ex);
}

// ---------------- message scatter (warp per edge) ----------------
template <int H>
__global__ __launch_bounds__(256) void scatter_kernel(
    const int* __restrict__ ei, int E,
    const float* __restrict__ v, const float* __restrict__ eemb,
    const float* __restrict__ score, const float* __restrict__ den,
    float* __restrict__ agg)
{
    int warp = (blockIdx.x * blockDim.x + threadIdx.x) >> 5;
    int lane = threadIdx.x & 31;
    if (warp >= E) return;
    int src = ei[warp];
    int dst = ei[E + warp];
    float alpha;
    if (H == 1) {
        alpha = score[warp] / (den[dst] + 1e-16f);
    } else {
        int h = lane >> 2;
        alpha = score[(size_t)warp * 8 + h] / (den[dst * 8 + h] + 1e-16f);
    }
    float4 vv = *reinterpret_cast<const float4*>(v + (size_t)src * 128 + lane * 4);
    float4 ev = *reinterpret_cast<const float4*>(eemb + (size_t)warp * 128 + lane * 4);
    float* base = agg + (size_t)dst * 128 + lane * 4;
    atomicAdd(base + 0, (vv.x + ev.x) * alpha);
    atomicAdd(base + 1, (vv.y + ev.y) * alpha);
    atomicAdd(base + 2, (vv.z + ev.z) * alpha);
    atomicAdd(base + 3, (vv.w + ev.w) * alpha);
}

// ---------------- epilogue: skip add (+ optional leaky relu) ----------------
template <bool RELU>
__global__ __launch_bounds__(256) void finalize_kernel(
    const float* __restrict__ agg, const float* __restrict__ skip,
    float* __restrict__ out, int n)
{
    int idx = blockIdx.x * blockDim.x + threadIdx.x;
    if (idx >= n) return;
    float val = agg[idx] + skip[idx];
    if (RELU) val = val > 0.f ? val : 0.01f * val;
    out[idx] = val;
}

extern "C" void kernel_launch(void* const* d_in, const int* in_sizes, int n_in,
                              void* d_out, int out_size) {
    const float* x  = (const float*)d_in[0];
    const int*   ei = (const int*)d_in[1];
    const float* ea = (const float*)d_in[2];
    const float* Wq1 = (const float*)d_in[3],  *bq1 = (const float*)d_in[4];
    const float* Wk1 = (const float*)d_in[5],  *bk1 = (const float*)d_in[6];
    const float* Wv1 = (const float*)d_in[7],  *bv1 = (const float*)d_in[8];
    const float* We1 = (const float*)d_in[9],  *be1 = (const float*)d_in[10];
    const float* Ws1 = (const float*)d_in[11], *bs1 = (const float*)d_in[12];
    const float* Wq2 = (const float*)d_in[13], *bq2 = (const float*)d_in[14];
    const float* Wk2 = (const float*)d_in[15], *bk2 = (const float*)d_in[16];
    const float* Wv2 = (const float*)d_in[17], *bv2 = (const float*)d_in[18];
    const float* We2 = (const float*)d_in[19], *be2 = (const float*)d_in[20];
    const float* Ws2 = (const float*)d_in[21], *bs2 = (const float*)d_in[22];

    int Nn = in_sizes[0] / DIM;
    int Ee = in_sizes[1] / 2;

    float *q, *k, *v, *s, *h, *agg, *eemb, *score, *den;
    unsigned* smax;
    cudaGetSymbolAddress((void**)&q, g_q);
    cudaGetSymbolAddress((void**)&k, g_k);
    cudaGetSymbolAddress((void**)&v, g_v);
    cudaGetSymbolAddress((void**)&s, g_s);
    cudaGetSymbolAddress((void**)&h, g_h);
    cudaGetSymbolAddress((void**)&agg, g_agg);
    cudaGetSymbolAddress((void**)&eemb, g_e);
    cudaGetSymbolAddress((void**)&score, g_score);
    cudaGetSymbolAddress((void**)&den, g_den);
    cudaGetSymbolAddress((void**)&smax, g_smax);

    dim3 gemmGrid((Nn + 127) / 128, 4);
    int egBlocks = (Ee + 127) / 128;
    int warpBlocks = (Ee + 7) / 8;   // 8 warps per 256-thread block

    // ---------------- layer 1 (heads=8, C=16) ----------------
    gemm_qkvs<<<gemmGrid, 256>>>(x, Nn, Wq1, Wk1, Wv1, Ws1,
                                 bq1, bk1, bv1, bs1, q, k, v, s);
    gemm_edge<<<egBlocks, 256>>>(ea, Ee, We1, be1, eemb);
    cudaMemsetAsync(smax, 0, (size_t)Nn * 8 * sizeof(unsigned));
    cudaMemsetAsync(den, 0, (size_t)Nn * 8 * sizeof(float));
    cudaMemsetAsync(agg, 0, (size_t)Nn * DIM * sizeof(float));
    score_kernel<8><<<warpBlocks, 256>>>(ei, Ee, q, k, eemb, score, smax, 0.25f);
    expsum_kernel<8><<<(Ee * 8 + 255) / 256, 256>>>(ei, Ee, score, smax, den);
    scatter_kernel<8><<<warpBlocks, 256>>>(ei, Ee, v, eemb, score, den, agg);
    finalize_kernel<true><<<(Nn * DIM + 255) / 256, 256>>>(agg, s, h, Nn * DIM);

    // ---------------- layer 2 (heads=1, C=128) ----------------
    gemm_qkvs<<<gemmGrid, 256>>>(h, Nn, Wq2, Wk2, Wv2, Ws2,
                                 bq2, bk2, bv2, bs2, q, k, v, s);
    gemm_edge<<<egBlocks, 256>>>(ea, Ee, We2, be2, eemb);
    cudaMemsetAsync(smax, 0, (size_t)Nn * sizeof(unsigned));
    cudaMemsetAsync(den, 0, (size_t)Nn * sizeof(float));
    cudaMemsetAsync(agg, 0, (size_t)Nn * DIM * sizeof(float));
    score_kernel<1><<<warpBlocks, 256>>>(ei, Ee, q, k, eemb, score, smax,
                                         0.08838834764831845f);
    expsum_kernel<1><<<(Ee + 255) / 256, 256>>>(ei, Ee, score, smax, den);
    scatter_kernel<1><<<warpBlocks, 256>>>(ei, Ee, v, eemb, score, den, agg);
    finalize_kernel<false><<<(Nn * DIM + 255) / 256, 256>>>(agg, s, (float*)d_out,
                                                            Nn * DIM);
}